// round 2
// baseline (speedup 1.0000x reference)
#include <cuda_runtime.h>
#include <cuda_bf16.h>

// Problem constants
#define NN 50000
#define NE 1600000
#define FEAT 1536
#define KH 768
#define HID 200
#define H2 400       // both branches concatenated
#define NCLS 2

// Scratch (static device allocations -- allowed)
__device__ float g_H[(size_t)NN * H2];     // 80 MB: h = x@W1 (both branches)
__device__ float g_AGG[(size_t)NN * H2];   // 80 MB: segment_sum of layer-1 msgs
__device__ float g_T[(size_t)NN * 4];      // layer-2 pre-msg: relu(agg+b1) @ W2 (both branches)
__device__ float g_AGG2[(size_t)NN * 4];   // segment_sum of layer-2 msgs

// ---------------------------------------------------------------------------
// Zero kernels referencing device globals directly (no symbol-address API)
// ---------------------------------------------------------------------------
__global__ void zero_agg_kernel() {
    int i = blockIdx.x * blockDim.x + threadIdx.x;
    if (i < NN * H2 / 4)
        reinterpret_cast<float4*>(g_AGG)[i] = make_float4(0.f, 0.f, 0.f, 0.f);
}
__global__ void zero_agg2_kernel() {
    int i = blockIdx.x * blockDim.x + threadIdx.x;
    if (i < NN)
        reinterpret_cast<float4*>(g_AGG2)[i] = make_float4(0.f, 0.f, 0.f, 0.f);
}

// ---------------------------------------------------------------------------
// GEMM1: H[n, 0:200]   = x[n, 0:768]    @ W1a
//        H[n, 200:400] = x[n, 768:1536] @ W1b
// BM=64, BN=64, BK=16, 256 threads, 4x4 microtile.
// grid.y in [0,8): tiles 0..3 = branch A cols, 4..7 = branch B cols
// ---------------------------------------------------------------------------
#define BM 64
#define BN 64
#define BK 16

__global__ void gemm1_kernel(const float* __restrict__ x,
                             const float* __restrict__ W1a,
                             const float* __restrict__ W1b) {
    __shared__ float As[BK][BM];
    __shared__ float Bs[BK][BN];

    const int t = threadIdx.x;
    const int m0 = blockIdx.x * BM;
    const int nt = blockIdx.y;
    const int branch = nt >> 2;
    const int col0 = (nt & 3) * BN;
    const float* __restrict__ W = branch ? W1b : W1a;
    const int xoff = branch * KH;

    const int ty = t >> 4;       // 0..15
    const int tx = t & 15;       // 0..15

    // A-load mapping: each thread loads one float4 along K
    const int aRow = t >> 2;          // 0..63
    const int aK   = (t & 3) * 4;     // 0,4,8,12
    // B-load mapping
    const int bK = t >> 4;            // 0..15
    const int bC = (t & 15) * 4;      // 0..60

    const bool aValid = (m0 + aRow) < NN;
    const float* xrow = x + (size_t)(m0 + aRow) * FEAT + xoff;

    float acc[4][4];
#pragma unroll
    for (int i = 0; i < 4; i++)
#pragma unroll
        for (int j = 0; j < 4; j++) acc[i][j] = 0.f;

    for (int k0 = 0; k0 < KH; k0 += BK) {
        // Load A tile (transposed into As[k][m])
        float4 av = make_float4(0.f, 0.f, 0.f, 0.f);
        if (aValid) av = *reinterpret_cast<const float4*>(xrow + k0 + aK);
        As[aK + 0][aRow] = av.x;
        As[aK + 1][aRow] = av.y;
        As[aK + 2][aRow] = av.z;
        As[aK + 3][aRow] = av.w;

        // Load B tile: W[(k0+bK), col0+bC .. +3] ; W is [768, 200] row-major
        float4 bv = make_float4(0.f, 0.f, 0.f, 0.f);
        const int c = col0 + bC;
        const float* wrow = W + (size_t)(k0 + bK) * HID;
        if (c + 3 < HID) {
            bv.x = wrow[c + 0]; bv.y = wrow[c + 1];
            bv.z = wrow[c + 2]; bv.w = wrow[c + 3];
        } else {
            if (c + 0 < HID) bv.x = wrow[c + 0];
            if (c + 1 < HID) bv.y = wrow[c + 1];
            if (c + 2 < HID) bv.z = wrow[c + 2];
            if (c + 3 < HID) bv.w = wrow[c + 3];
        }
        *reinterpret_cast<float4*>(&Bs[bK][bC]) = bv;

        __syncthreads();

#pragma unroll
        for (int k = 0; k < BK; k++) {
            float4 a = *reinterpret_cast<const float4*>(&As[k][ty * 4]);
            float4 b = *reinterpret_cast<const float4*>(&Bs[k][tx * 4]);
            acc[0][0] += a.x * b.x; acc[0][1] += a.x * b.y; acc[0][2] += a.x * b.z; acc[0][3] += a.x * b.w;
            acc[1][0] += a.y * b.x; acc[1][1] += a.y * b.y; acc[1][2] += a.y * b.z; acc[1][3] += a.y * b.w;
            acc[2][0] += a.z * b.x; acc[2][1] += a.z * b.y; acc[2][2] += a.z * b.z; acc[2][3] += a.z * b.w;
            acc[3][0] += a.w * b.x; acc[3][1] += a.w * b.y; acc[3][2] += a.w * b.z; acc[3][3] += a.w * b.w;
        }
        __syncthreads();
    }

    // Store: H[row, branch*200 + col]
#pragma unroll
    for (int i = 0; i < 4; i++) {
        const int row = m0 + ty * 4 + i;
        if (row >= NN) continue;
#pragma unroll
        for (int j = 0; j < 4; j++) {
            const int c = col0 + tx * 4 + j;
            if (c < HID) g_H[(size_t)row * H2 + branch * HID + c] = acc[i][j];
        }
    }
}

// ---------------------------------------------------------------------------
// Scatter layer 1: for each edge e, AGG[dst] += H[src] * w
// One thread per (edge, float4-chunk); 100 chunks per edge.
// Consecutive threads share an edge -> index loads broadcast, H reads coalesced.
// ---------------------------------------------------------------------------
__global__ void scatter1_kernel(const int* __restrict__ src,
                                const int* __restrict__ dst,
                                const float* __restrict__ w) {
    const long long i = (long long)blockIdx.x * blockDim.x + threadIdx.x;
    if (i >= (long long)NE * (H2 / 4)) return;
    const int e = (int)(i / (H2 / 4));
    const int c = (int)(i % (H2 / 4));
    const int s = __ldg(&src[e]);
    const int d = __ldg(&dst[e]);
    const float ww = __ldg(&w[e]);
    float4 h = *reinterpret_cast<const float4*>(&g_H[(size_t)s * H2 + c * 4]);
    h.x *= ww; h.y *= ww; h.z *= ww; h.w *= ww;
    atomicAdd(reinterpret_cast<float4*>(&g_AGG[(size_t)d * H2 + c * 4]), h);
}

// ---------------------------------------------------------------------------
// Layer-2 projection (fused relu + bias): T[n,0:2] = relu(AGG[n,0:200]+b1a) @ W2a
//                                         T[n,2:4] = relu(AGG[n,200:400]+b1b) @ W2b
// One warp per node; weights/biases staged in shared memory.
// ---------------------------------------------------------------------------
__global__ void proj2_kernel(const float* __restrict__ b1a,
                             const float* __restrict__ W2a,
                             const float* __restrict__ b1b,
                             const float* __restrict__ W2b) {
    __shared__ float sW2a[HID * 2];
    __shared__ float sW2b[HID * 2];
    __shared__ float sB1[2 * HID];

    const int t = threadIdx.x;  // 256
    for (int i = t; i < HID * 2; i += blockDim.x) { sW2a[i] = W2a[i]; sW2b[i] = W2b[i]; }
    for (int i = t; i < HID; i += blockDim.x)     { sB1[i] = b1a[i]; sB1[HID + i] = b1b[i]; }
    __syncthreads();

    const int warp = t >> 5;
    const int lane = t & 31;
    const int n = blockIdx.x * 8 + warp;
    if (n >= NN) return;

    float z0 = 0.f, z1 = 0.f, z2 = 0.f, z3 = 0.f;
    const float* agg = &g_AGG[(size_t)n * H2];
    for (int j = lane; j < HID; j += 32) {
        float a1 = agg[j] + sB1[j];
        a1 = a1 > 0.f ? a1 : 0.f;
        z0 += a1 * sW2a[j * 2 + 0];
        z1 += a1 * sW2a[j * 2 + 1];
        float a2 = agg[HID + j] + sB1[HID + j];
        a2 = a2 > 0.f ? a2 : 0.f;
        z2 += a2 * sW2b[j * 2 + 0];
        z3 += a2 * sW2b[j * 2 + 1];
    }
#pragma unroll
    for (int off = 16; off > 0; off >>= 1) {
        z0 += __shfl_down_sync(0xFFFFFFFFu, z0, off);
        z1 += __shfl_down_sync(0xFFFFFFFFu, z1, off);
        z2 += __shfl_down_sync(0xFFFFFFFFu, z2, off);
        z3 += __shfl_down_sync(0xFFFFFFFFu, z3, off);
    }
    if (lane == 0) {
        float4* out = reinterpret_cast<float4*>(&g_T[(size_t)n * 4]);
        *out = make_float4(z0, z1, z2, z3);
    }
}

// ---------------------------------------------------------------------------
// Scatter layer 2: AGG2[dst] += T[src] * w  (one thread per edge, float4 red)
// ---------------------------------------------------------------------------
__global__ void scatter2_kernel(const int* __restrict__ src,
                                const int* __restrict__ dst,
                                const float* __restrict__ w) {
    const int e = blockIdx.x * blockDim.x + threadIdx.x;
    if (e >= NE) return;
    const int s = __ldg(&src[e]);
    const int d = __ldg(&dst[e]);
    const float ww = __ldg(&w[e]);
    float4 tv = *reinterpret_cast<const float4*>(&g_T[(size_t)s * 4]);
    tv.x *= ww; tv.y *= ww; tv.z *= ww; tv.w *= ww;
    atomicAdd(reinterpret_cast<float4*>(&g_AGG2[(size_t)d * 4]), tv);
}

// ---------------------------------------------------------------------------
// Final: softmax each branch, elementwise max, renormalize
// ---------------------------------------------------------------------------
__global__ void final_kernel(const float* __restrict__ b2a,
                             const float* __restrict__ b2b,
                             float* __restrict__ out) {
    const int n = blockIdx.x * blockDim.x + threadIdx.x;
    if (n >= NN) return;
    float4 a = *reinterpret_cast<const float4*>(&g_AGG2[(size_t)n * 4]);
    // branch A softmax
    float za0 = a.x + b2a[0], za1 = a.y + b2a[1];
    float ma = fmaxf(za0, za1);
    float ea0 = expf(za0 - ma), ea1 = expf(za1 - ma);
    float sa = ea0 + ea1;
    float p10 = ea0 / sa, p11 = ea1 / sa;
    // branch B softmax
    float zb0 = a.z + b2b[0], zb1 = a.w + b2b[1];
    float mb = fmaxf(zb0, zb1);
    float eb0 = expf(zb0 - mb), eb1 = expf(zb1 - mb);
    float sb = eb0 + eb1;
    float p20 = eb0 / sb, p21 = eb1 / sb;
    // vote
    float v0 = fmaxf(p10, p20);
    float v1 = fmaxf(p11, p21);
    float inv = 1.f / (v0 + v1);
    out[n * 2 + 0] = v0 * inv;
    out[n * 2 + 1] = v1 * inv;
}

// ---------------------------------------------------------------------------
// Launch
// ---------------------------------------------------------------------------
extern "C" void kernel_launch(void* const* d_in, const int* in_sizes, int n_in,
                              void* d_out, int out_size) {
    const float* x        = (const float*)d_in[0];
    const int*   edge_src = (const int*)d_in[1];
    const int*   edge_dst = (const int*)d_in[2];
    const float* edge_w   = (const float*)d_in[3];
    const float* W1a      = (const float*)d_in[4];
    const float* b1a      = (const float*)d_in[5];
    const float* W2a      = (const float*)d_in[6];
    const float* b2a      = (const float*)d_in[7];
    const float* W1b      = (const float*)d_in[8];
    const float* b1b      = (const float*)d_in[9];
    const float* W2b      = (const float*)d_in[10];
    const float* b2b      = (const float*)d_in[11];
    float* out = (float*)d_out;

    // Zero accumulators (device-global symbols referenced directly in-kernel)
    zero_agg_kernel<<<(NN * H2 / 4 + 255) / 256, 256>>>();
    zero_agg2_kernel<<<(NN + 255) / 256, 256>>>();

    // GEMM1
    {
        dim3 grid((NN + BM - 1) / BM, 8);
        gemm1_kernel<<<grid, 256>>>(x, W1a, W1b);
    }

    // Scatter layer 1
    {
        long long total = (long long)NE * (H2 / 4);
        int blocks = (int)((total + 255) / 256);
        scatter1_kernel<<<blocks, 256>>>(edge_src, edge_dst, edge_w);
    }

    // Projection (relu+bias fused) -> T
    {
        int blocks = (NN + 7) / 8;
        proj2_kernel<<<blocks, 256>>>(b1a, W2a, b1b, W2b);
    }

    // Scatter layer 2
    {
        int blocks = (NE + 255) / 256;
        scatter2_kernel<<<blocks, 256>>>(edge_src, edge_dst, edge_w);
    }

    // Final vote
    {
        int blocks = (NN + 255) / 256;
        final_kernel<<<blocks, 256>>>(b2a, b2b, out);
    }
}

// round 3
// speedup vs baseline: 1.6370x; 1.6370x over previous
#include <cuda_runtime.h>
#include <cuda_bf16.h>
#include <cstdint>

// Problem constants
#define NN 50000
#define NE 1600000
#define FEAT 1536
#define KH 768
#define HID 200
#define H2 400       // both branches concatenated
#define NCLS 2

// Scratch (static device allocations -- allowed)
__device__ float g_H[(size_t)NN * H2];     // 80 MB: h = x@W1 (both branches)
__device__ float g_AGG[(size_t)NN * H2];   // 80 MB: segment_sum of layer-1 msgs
__device__ float g_T[(size_t)NN * 4];      // layer-2 pre-msg
__device__ float g_AGG2[(size_t)NN * 4];   // segment_sum of layer-2 msgs

// ---------------------------------------------------------------------------
// Zero kernels
// ---------------------------------------------------------------------------
__global__ void zero_agg_kernel() {
    int i = blockIdx.x * blockDim.x + threadIdx.x;
    if (i < NN * H2 / 4)
        reinterpret_cast<float4*>(g_AGG)[i] = make_float4(0.f, 0.f, 0.f, 0.f);
}
__global__ void zero_agg2_kernel() {
    int i = blockIdx.x * blockDim.x + threadIdx.x;
    if (i < NN)
        reinterpret_cast<float4*>(g_AGG2)[i] = make_float4(0.f, 0.f, 0.f, 0.f);
}

// ---------------------------------------------------------------------------
// GEMM1 (tf32 tensor core):
//   H[n, 0:200]   = x[n, 0:768]    @ W1a
//   H[n, 200:400] = x[n, 768:1536] @ W1b
// BM=128, BN=64, BK=16. 256 threads = 8 warps (4m x 2n), warp tile 32x32.
// mma.sync.m16n8k8 tf32, fp32 accumulate.
// grid.x = 8 col-tiles (fastest -> L2 reuse of x rows), grid.y = M tiles.
// ---------------------------------------------------------------------------
#define GBM 128
#define GBN 64
#define GBK 16
#define ASTR 20   // As row stride (floats): conflict-free A-frag reads
#define BSTR 72   // Bs row stride (floats): conflict-free B-frag reads

__device__ __forceinline__ uint32_t f2tf32(float f) {
    uint32_t r;
    asm volatile("cvt.rna.tf32.f32 %0, %1;" : "=r"(r) : "f"(f));
    return r;
}

__global__ void __launch_bounds__(256)
gemm1_tf32_kernel(const float* __restrict__ x,
                  const float* __restrict__ W1a,
                  const float* __restrict__ W1b) {
    __shared__ float As[GBM * ASTR];   // As[m][k], stride 20
    __shared__ float Bs[GBK * BSTR];   // Bs[k][n], stride 72

    const int t = threadIdx.x;
    const int warp = t >> 5;
    const int lane = t & 31;

    const int nt = blockIdx.x;            // 0..7
    const int branch = nt >> 2;
    const int col0 = (nt & 3) * GBN;      // 0,64,128,192
    const int m0 = blockIdx.y * GBM;

    const float* __restrict__ W = branch ? W1b : W1a;
    const int xoff = branch * KH;

    // Warp tiling: 4 m-warps x 2 n-warps
    const int wm0 = (warp >> 1) * 32;     // 0,32,64,96
    const int wn0 = (warp & 1) * 32;      // 0,32

    // Global A load mapping: per iter thread loads float4 at (row = t>>2, k4 = (t&3)*4),
    // two iters covering rows 0..63 and 64..127.
    const int aRow = t >> 2;              // 0..63
    const int aK4  = (t & 3) * 4;
    // Global B load mapping: thread loads float4 at (k = t>>4, c4 = (t&15)*4)
    const int bK = t >> 4;                // 0..15
    const int bC4 = (t & 15) * 4;         // 0..60

    // Accumulators: 2 m-frags x 4 n-frags x 4 regs
    float acc[2][4][4];
#pragma unroll
    for (int i = 0; i < 2; i++)
#pragma unroll
        for (int j = 0; j < 4; j++)
#pragma unroll
            for (int r = 0; r < 4; r++) acc[i][j][r] = 0.f;

    const int lq = lane >> 2;   // 0..7
    const int lr = lane & 3;    // 0..3

    for (int k0 = 0; k0 < KH; k0 += GBK) {
        // ---- load A tile: x[m0..m0+127, xoff+k0 .. +15] -> As[m][k]
#pragma unroll
        for (int half = 0; half < 2; half++) {
            const int row = aRow + half * 64;
            float4 av = make_float4(0.f, 0.f, 0.f, 0.f);
            if (m0 + row < NN)
                av = *reinterpret_cast<const float4*>(
                    x + (size_t)(m0 + row) * FEAT + xoff + k0 + aK4);
            *reinterpret_cast<float4*>(&As[row * ASTR + aK4]) = av;
        }
        // ---- load B tile: W[k0+bK, col0+bC4 .. +3] -> Bs[k][n]
        {
            float4 bv = make_float4(0.f, 0.f, 0.f, 0.f);
            const int c = col0 + bC4;
            const float* wrow = W + (size_t)(k0 + bK) * HID;
            if (c + 3 < HID) {
                bv = make_float4(wrow[c], wrow[c + 1], wrow[c + 2], wrow[c + 3]);
            } else {
                if (c + 0 < HID) bv.x = wrow[c + 0];
                if (c + 1 < HID) bv.y = wrow[c + 1];
                if (c + 2 < HID) bv.z = wrow[c + 2];
                if (c + 3 < HID) bv.w = wrow[c + 3];
            }
            *reinterpret_cast<float4*>(&Bs[bK * BSTR + bC4]) = bv;
        }
        __syncthreads();

        // ---- 2 k-steps of 8
#pragma unroll
        for (int ks = 0; ks < 2; ks++) {
            const int kb = ks * 8;
            // A fragments: 2 m16 frags
            uint32_t afr[2][4];
#pragma unroll
            for (int mf = 0; mf < 2; mf++) {
                const int mr = wm0 + mf * 16 + lq;
                afr[mf][0] = f2tf32(As[(mr + 0) * ASTR + kb + lr]);
                afr[mf][1] = f2tf32(As[(mr + 8) * ASTR + kb + lr]);
                afr[mf][2] = f2tf32(As[(mr + 0) * ASTR + kb + lr + 4]);
                afr[mf][3] = f2tf32(As[(mr + 8) * ASTR + kb + lr + 4]);
            }
            // B fragments: 4 n8 frags
            uint32_t bfr[4][2];
#pragma unroll
            for (int nf = 0; nf < 4; nf++) {
                const int nc = wn0 + nf * 8 + lq;
                bfr[nf][0] = f2tf32(Bs[(kb + lr + 0) * BSTR + nc]);
                bfr[nf][1] = f2tf32(Bs[(kb + lr + 4) * BSTR + nc]);
            }
#pragma unroll
            for (int mf = 0; mf < 2; mf++)
#pragma unroll
                for (int nf = 0; nf < 4; nf++) {
                    asm volatile(
                        "mma.sync.aligned.m16n8k8.row.col.f32.tf32.tf32.f32 "
                        "{%0,%1,%2,%3}, {%4,%5,%6,%7}, {%8,%9}, {%0,%1,%2,%3};"
                        : "+f"(acc[mf][nf][0]), "+f"(acc[mf][nf][1]),
                          "+f"(acc[mf][nf][2]), "+f"(acc[mf][nf][3])
                        : "r"(afr[mf][0]), "r"(afr[mf][1]),
                          "r"(afr[mf][2]), "r"(afr[mf][3]),
                          "r"(bfr[nf][0]), "r"(bfr[nf][1]));
                }
        }
        __syncthreads();
    }

    // ---- epilogue: C frag (mf,nf): row = wm0+mf*16+lq+{0,8}, col = wn0+nf*8+2*lr+{0,1}
#pragma unroll
    for (int mf = 0; mf < 2; mf++) {
#pragma unroll
        for (int nf = 0; nf < 4; nf++) {
            const int r0 = m0 + wm0 + mf * 16 + lq;
            const int c0 = col0 + wn0 + nf * 8 + 2 * lr;
#pragma unroll
            for (int rr = 0; rr < 2; rr++) {
                const int row = r0 + rr * 8;
                if (row >= NN) continue;
#pragma unroll
                for (int cc = 0; cc < 2; cc++) {
                    const int c = c0 + cc;
                    if (c < HID)
                        g_H[(size_t)row * H2 + branch * HID + c] = acc[mf][nf][rr * 2 + cc];
                }
            }
        }
    }
}

// ---------------------------------------------------------------------------
// Scatter layer 1: AGG[dst] += H[src] * w  (thread per (edge, float4-chunk))
// ---------------------------------------------------------------------------
__global__ void scatter1_kernel(const int* __restrict__ src,
                                const int* __restrict__ dst,
                                const float* __restrict__ w) {
    const long long i = (long long)blockIdx.x * blockDim.x + threadIdx.x;
    if (i >= (long long)NE * (H2 / 4)) return;
    const int e = (int)(i / (H2 / 4));
    const int c = (int)(i % (H2 / 4));
    const int s = __ldg(&src[e]);
    const int d = __ldg(&dst[e]);
    const float ww = __ldg(&w[e]);
    float4 h = *reinterpret_cast<const float4*>(&g_H[(size_t)s * H2 + c * 4]);
    h.x *= ww; h.y *= ww; h.z *= ww; h.w *= ww;
    atomicAdd(reinterpret_cast<float4*>(&g_AGG[(size_t)d * H2 + c * 4]), h);
}

// ---------------------------------------------------------------------------
// Layer-2 projection (fused relu + bias)
// ---------------------------------------------------------------------------
__global__ void proj2_kernel(const float* __restrict__ b1a,
                             const float* __restrict__ W2a,
                             const float* __restrict__ b1b,
                             const float* __restrict__ W2b) {
    __shared__ float sW2a[HID * 2];
    __shared__ float sW2b[HID * 2];
    __shared__ float sB1[2 * HID];

    const int t = threadIdx.x;  // 256
    for (int i = t; i < HID * 2; i += blockDim.x) { sW2a[i] = W2a[i]; sW2b[i] = W2b[i]; }
    for (int i = t; i < HID; i += blockDim.x)     { sB1[i] = b1a[i]; sB1[HID + i] = b1b[i]; }
    __syncthreads();

    const int warp = t >> 5;
    const int lane = t & 31;
    const int n = blockIdx.x * 8 + warp;
    if (n >= NN) return;

    float z0 = 0.f, z1 = 0.f, z2 = 0.f, z3 = 0.f;
    const float* agg = &g_AGG[(size_t)n * H2];
    for (int j = lane; j < HID; j += 32) {
        float a1 = agg[j] + sB1[j];
        a1 = a1 > 0.f ? a1 : 0.f;
        z0 += a1 * sW2a[j * 2 + 0];
        z1 += a1 * sW2a[j * 2 + 1];
        float a2 = agg[HID + j] + sB1[HID + j];
        a2 = a2 > 0.f ? a2 : 0.f;
        z2 += a2 * sW2b[j * 2 + 0];
        z3 += a2 * sW2b[j * 2 + 1];
    }
#pragma unroll
    for (int off = 16; off > 0; off >>= 1) {
        z0 += __shfl_down_sync(0xFFFFFFFFu, z0, off);
        z1 += __shfl_down_sync(0xFFFFFFFFu, z1, off);
        z2 += __shfl_down_sync(0xFFFFFFFFu, z2, off);
        z3 += __shfl_down_sync(0xFFFFFFFFu, z3, off);
    }
    if (lane == 0) {
        float4* out = reinterpret_cast<float4*>(&g_T[(size_t)n * 4]);
        *out = make_float4(z0, z1, z2, z3);
    }
}

// ---------------------------------------------------------------------------
// Scatter layer 2
// ---------------------------------------------------------------------------
__global__ void scatter2_kernel(const int* __restrict__ src,
                                const int* __restrict__ dst,
                                const float* __restrict__ w) {
    const int e = blockIdx.x * blockDim.x + threadIdx.x;
    if (e >= NE) return;
    const int s = __ldg(&src[e]);
    const int d = __ldg(&dst[e]);
    const float ww = __ldg(&w[e]);
    float4 tv = *reinterpret_cast<const float4*>(&g_T[(size_t)s * 4]);
    tv.x *= ww; tv.y *= ww; tv.z *= ww; tv.w *= ww;
    atomicAdd(reinterpret_cast<float4*>(&g_AGG2[(size_t)d * 4]), tv);
}

// ---------------------------------------------------------------------------
// Final: softmax each branch, elementwise max, renormalize
// ---------------------------------------------------------------------------
__global__ void final_kernel(const float* __restrict__ b2a,
                             const float* __restrict__ b2b,
                             float* __restrict__ out) {
    const int n = blockIdx.x * blockDim.x + threadIdx.x;
    if (n >= NN) return;
    float4 a = *reinterpret_cast<const float4*>(&g_AGG2[(size_t)n * 4]);
    float za0 = a.x + b2a[0], za1 = a.y + b2a[1];
    float ma = fmaxf(za0, za1);
    float ea0 = expf(za0 - ma), ea1 = expf(za1 - ma);
    float sa = ea0 + ea1;
    float p10 = ea0 / sa, p11 = ea1 / sa;
    float zb0 = a.z + b2b[0], zb1 = a.w + b2b[1];
    float mb = fmaxf(zb0, zb1);
    float eb0 = expf(zb0 - mb), eb1 = expf(zb1 - mb);
    float sb = eb0 + eb1;
    float p20 = eb0 / sb, p21 = eb1 / sb;
    float v0 = fmaxf(p10, p20);
    float v1 = fmaxf(p11, p21);
    float inv = 1.f / (v0 + v1);
    out[n * 2 + 0] = v0 * inv;
    out[n * 2 + 1] = v1 * inv;
}

// ---------------------------------------------------------------------------
// Launch
// ---------------------------------------------------------------------------
extern "C" void kernel_launch(void* const* d_in, const int* in_sizes, int n_in,
                              void* d_out, int out_size) {
    const float* x        = (const float*)d_in[0];
    const int*   edge_src = (const int*)d_in[1];
    const int*   edge_dst = (const int*)d_in[2];
    const float* edge_w   = (const float*)d_in[3];
    const float* W1a      = (const float*)d_in[4];
    const float* b1a      = (const float*)d_in[5];
    const float* W2a      = (const float*)d_in[6];
    const float* b2a      = (const float*)d_in[7];
    const float* W1b      = (const float*)d_in[8];
    const float* b1b      = (const float*)d_in[9];
    const float* W2b      = (const float*)d_in[10];
    const float* b2b      = (const float*)d_in[11];
    float* out = (float*)d_out;

    zero_agg_kernel<<<(NN * H2 / 4 + 255) / 256, 256>>>();
    zero_agg2_kernel<<<(NN + 255) / 256, 256>>>();

    // GEMM1 (tf32 tensor core); col-tiles fastest for L2 reuse of x
    {
        dim3 grid(8, (NN + GBM - 1) / GBM);
        gemm1_tf32_kernel<<<grid, 256>>>(x, W1a, W1b);
    }

    // Scatter layer 1
    {
        long long total = (long long)NE * (H2 / 4);
        int blocks = (int)((total + 255) / 256);
        scatter1_kernel<<<blocks, 256>>>(edge_src, edge_dst, edge_w);
    }

    // Projection (relu+bias fused) -> T
    proj2_kernel<<<(NN + 7) / 8, 256>>>(b1a, W2a, b1b, W2b);

    // Scatter layer 2
    scatter2_kernel<<<(NE + 255) / 256, 256>>>(edge_src, edge_dst, edge_w);

    // Final vote
    final_kernel<<<(NN + 255) / 256, 256>>>(b2a, b2b, out);
}

// round 11
// speedup vs baseline: 2.8460x; 1.7386x over previous
#include <cuda_runtime.h>
#include <cuda_bf16.h>
#include <cstdint>

// Problem constants
#define NN 50000
#define NE 1600000
#define FEAT 1536
#define KH 768
#define HID 200
#define H2 400
#define NCLS 2

// Scratch
__device__ float g_H[(size_t)NN * H2];   // 80 MB: h = x@W1 (both branches)
__device__ float g_T[(size_t)NN * 4];    // layer-2 pre-msg per node
__device__ int   g_deg[NN];              // degree histogram
__device__ int   g_cur[NN];              // fill cursors
__device__ int   g_off[NN + 1];          // CSR row offsets (by dst)
__device__ int   g_csr_src[NE];          // src per CSR slot
__device__ float g_csr_w[NE];            // weight per CSR slot

// ---------------------------------------------------------------------------
// CSR build
// ---------------------------------------------------------------------------
__global__ void zero_counts_kernel() {
    int i = blockIdx.x * blockDim.x + threadIdx.x;
    if (i < NN) { g_deg[i] = 0; g_cur[i] = 0; }
}

__global__ void hist_kernel(const int* __restrict__ dst) {
    int e = blockIdx.x * blockDim.x + threadIdx.x;
    if (e < NE) atomicAdd(&g_deg[dst[e]], 1);
}

// Single-block exclusive scan over g_deg -> g_off
__global__ void scan_kernel() {
    __shared__ int part[1024];
    const int tid = threadIdx.x;
    const int chunk = (NN + 1023) / 1024;   // 49
    const int start = tid * chunk;
    const int stop = min(start + chunk, NN);

    int sum = 0;
    for (int i = start; i < stop; i++) sum += g_deg[i];
    part[tid] = sum;
    __syncthreads();

    // Hillis-Steele inclusive scan
    for (int off = 1; off < 1024; off <<= 1) {
        int v = (tid >= off) ? part[tid - off] : 0;
        __syncthreads();
        part[tid] += v;
        __syncthreads();
    }

    int running = (tid == 0) ? 0 : part[tid - 1];
    for (int i = start; i < stop; i++) {
        g_off[i] = running;
        running += g_deg[i];
    }
    if (tid == 0) g_off[NN] = NE;
}

__global__ void fill_kernel(const int* __restrict__ src,
                            const int* __restrict__ dst,
                            const float* __restrict__ w) {
    int e = blockIdx.x * blockDim.x + threadIdx.x;
    if (e >= NE) return;
    const int d = dst[e];
    const int pos = g_off[d] + atomicAdd(&g_cur[d], 1);
    g_csr_src[pos] = src[e];
    g_csr_w[pos] = w[e];
}

// ---------------------------------------------------------------------------
// GEMM1 (tf32 tensor core): H[n,0:200] = x[n,0:768]@W1a ; H[n,200:400] = x[n,768:]@W1b
// ---------------------------------------------------------------------------
#define GBM 128
#define GBN 64
#define GBK 16
#define ASTR 20
#define BSTR 72

__device__ __forceinline__ uint32_t f2tf32(float f) {
    uint32_t r;
    asm volatile("cvt.rna.tf32.f32 %0, %1;" : "=r"(r) : "f"(f));
    return r;
}

__global__ void __launch_bounds__(256)
gemm1_tf32_kernel(const float* __restrict__ x,
                  const float* __restrict__ W1a,
                  const float* __restrict__ W1b) {
    __shared__ float As[GBM * ASTR];
    __shared__ float Bs[GBK * BSTR];

    const int t = threadIdx.x;
    const int warp = t >> 5;
    const int lane = t & 31;

    const int nt = blockIdx.x;            // 0..7
    const int branch = nt >> 2;
    const int col0 = (nt & 3) * GBN;
    const int m0 = blockIdx.y * GBM;

    const float* __restrict__ W = branch ? W1b : W1a;
    const int xoff = branch * KH;

    const int wm0 = (warp >> 1) * 32;
    const int wn0 = (warp & 1) * 32;

    const int aRow = t >> 2;
    const int aK4  = (t & 3) * 4;
    const int bK = t >> 4;
    const int bC4 = (t & 15) * 4;

    float acc[2][4][4];
#pragma unroll
    for (int i = 0; i < 2; i++)
#pragma unroll
        for (int j = 0; j < 4; j++)
#pragma unroll
            for (int r = 0; r < 4; r++) acc[i][j][r] = 0.f;

    const int lq = lane >> 2;
    const int lr = lane & 3;

    for (int k0 = 0; k0 < KH; k0 += GBK) {
#pragma unroll
        for (int half = 0; half < 2; half++) {
            const int row = aRow + half * 64;
            float4 av = make_float4(0.f, 0.f, 0.f, 0.f);
            if (m0 + row < NN)
                av = *reinterpret_cast<const float4*>(
                    x + (size_t)(m0 + row) * FEAT + xoff + k0 + aK4);
            *reinterpret_cast<float4*>(&As[row * ASTR + aK4]) = av;
        }
        {
            float4 bv = make_float4(0.f, 0.f, 0.f, 0.f);
            const int c = col0 + bC4;
            const float* wrow = W + (size_t)(k0 + bK) * HID;
            if (c + 3 < HID) {
                bv = make_float4(wrow[c], wrow[c + 1], wrow[c + 2], wrow[c + 3]);
            } else {
                if (c + 0 < HID) bv.x = wrow[c + 0];
                if (c + 1 < HID) bv.y = wrow[c + 1];
                if (c + 2 < HID) bv.z = wrow[c + 2];
                if (c + 3 < HID) bv.w = wrow[c + 3];
            }
            *reinterpret_cast<float4*>(&Bs[bK * BSTR + bC4]) = bv;
        }
        __syncthreads();

#pragma unroll
        for (int ks = 0; ks < 2; ks++) {
            const int kb = ks * 8;
            uint32_t afr[2][4];
#pragma unroll
            for (int mf = 0; mf < 2; mf++) {
                const int mr = wm0 + mf * 16 + lq;
                afr[mf][0] = f2tf32(As[(mr + 0) * ASTR + kb + lr]);
                afr[mf][1] = f2tf32(As[(mr + 8) * ASTR + kb + lr]);
                afr[mf][2] = f2tf32(As[(mr + 0) * ASTR + kb + lr + 4]);
                afr[mf][3] = f2tf32(As[(mr + 8) * ASTR + kb + lr + 4]);
            }
            uint32_t bfr[4][2];
#pragma unroll
            for (int nf = 0; nf < 4; nf++) {
                const int nc = wn0 + nf * 8 + lq;
                bfr[nf][0] = f2tf32(Bs[(kb + lr + 0) * BSTR + nc]);
                bfr[nf][1] = f2tf32(Bs[(kb + lr + 4) * BSTR + nc]);
            }
#pragma unroll
            for (int mf = 0; mf < 2; mf++)
#pragma unroll
                for (int nf = 0; nf < 4; nf++) {
                    asm volatile(
                        "mma.sync.aligned.m16n8k8.row.col.f32.tf32.tf32.f32 "
                        "{%0,%1,%2,%3}, {%4,%5,%6,%7}, {%8,%9}, {%0,%1,%2,%3};"
                        : "+f"(acc[mf][nf][0]), "+f"(acc[mf][nf][1]),
                          "+f"(acc[mf][nf][2]), "+f"(acc[mf][nf][3])
                        : "r"(afr[mf][0]), "r"(afr[mf][1]),
                          "r"(afr[mf][2]), "r"(afr[mf][3]),
                          "r"(bfr[nf][0]), "r"(bfr[nf][1]));
                }
        }
        __syncthreads();
    }

#pragma unroll
    for (int mf = 0; mf < 2; mf++) {
#pragma unroll
        for (int nf = 0; nf < 4; nf++) {
            const int r0 = m0 + wm0 + mf * 16 + lq;
            const int c0 = col0 + wn0 + nf * 8 + 2 * lr;
#pragma unroll
            for (int rr = 0; rr < 2; rr++) {
                const int row = r0 + rr * 8;
                if (row >= NN) continue;
#pragma unroll
                for (int cc = 0; cc < 2; cc++) {
                    const int c = c0 + cc;
                    if (c < HID)
                        g_H[(size_t)row * H2 + branch * HID + c] = acc[mf][nf][rr * 2 + cc];
                }
            }
        }
    }
}

// ---------------------------------------------------------------------------
// agg1: warp per dst node. Register-accumulate agg = sum_e w_e * H[src_e]
// (4 float4 chunks per lane covering 400 cols), then fused relu+bias+W2
// projection -> T[n] (4 floats). No AGG buffer, no atomics.
// ---------------------------------------------------------------------------
__global__ void __launch_bounds__(256)
agg1_kernel(const float* __restrict__ b1a,
            const float* __restrict__ W2a,
            const float* __restrict__ b1b,
            const float* __restrict__ W2b) {
    __shared__ float sW2a[HID * 2];
    __shared__ float sW2b[HID * 2];
    __shared__ float sB1[2 * HID];

    const int t = threadIdx.x;
    for (int i = t; i < HID * 2; i += blockDim.x) { sW2a[i] = W2a[i]; sW2b[i] = W2b[i]; }
    for (int i = t; i < HID; i += blockDim.x)     { sB1[i] = b1a[i]; sB1[HID + i] = b1b[i]; }
    __syncthreads();

    const int warp = t >> 5;
    const int lane = t & 31;
    const int n = blockIdx.x * 8 + warp;
    if (n >= NN) return;

    const int beg = g_off[n];
    const int end = g_off[n + 1];

    float4 acc[4];
#pragma unroll
    for (int m = 0; m < 4; m++) acc[m] = make_float4(0.f, 0.f, 0.f, 0.f);

    for (int e = beg; e < end; e++) {
        const int s = __ldg(&g_csr_src[e]);
        const float ww = __ldg(&g_csr_w[e]);
        const float4* hp = reinterpret_cast<const float4*>(g_H + (size_t)s * H2);
#pragma unroll
        for (int m = 0; m < 4; m++) {
            const int chunk = lane + m * 32;
            if (chunk < 100) {
                float4 h = __ldg(&hp[chunk]);
                acc[m].x += ww * h.x;
                acc[m].y += ww * h.y;
                acc[m].z += ww * h.z;
                acc[m].w += ww * h.w;
            }
        }
    }

    // Fused relu + bias + projection
    float z0 = 0.f, z1 = 0.f, z2 = 0.f, z3 = 0.f;
#pragma unroll
    for (int m = 0; m < 4; m++) {
        const int chunk = lane + m * 32;
        if (chunk >= 100) continue;
        const float av[4] = {acc[m].x, acc[m].y, acc[m].z, acc[m].w};
#pragma unroll
        for (int k = 0; k < 4; k++) {
            const int col = chunk * 4 + k;        // 0..399
            float a = av[k] + sB1[col];
            a = a > 0.f ? a : 0.f;
            if (col < HID) {
                z0 += a * sW2a[col * 2 + 0];
                z1 += a * sW2a[col * 2 + 1];
            } else {
                const int c2 = col - HID;
                z2 += a * sW2b[c2 * 2 + 0];
                z3 += a * sW2b[c2 * 2 + 1];
            }
        }
    }
#pragma unroll
    for (int off = 16; off > 0; off >>= 1) {
        z0 += __shfl_down_sync(0xFFFFFFFFu, z0, off);
        z1 += __shfl_down_sync(0xFFFFFFFFu, z1, off);
        z2 += __shfl_down_sync(0xFFFFFFFFu, z2, off);
        z3 += __shfl_down_sync(0xFFFFFFFFu, z3, off);
    }
    if (lane == 0)
        *reinterpret_cast<float4*>(&g_T[(size_t)n * 4]) = make_float4(z0, z1, z2, z3);
}

// ---------------------------------------------------------------------------
// agg2: warp per dst node. Gather T[src]*w, reduce, softmax both branches,
// vote, renormalize, write out. No atomics, no AGG2.
// ---------------------------------------------------------------------------
__global__ void __launch_bounds__(256)
agg2_kernel(const float* __restrict__ b2a,
            const float* __restrict__ b2b,
            float* __restrict__ out) {
    const int t = threadIdx.x;
    const int warp = t >> 5;
    const int lane = t & 31;
    const int n = blockIdx.x * 8 + warp;
    if (n >= NN) return;

    const int beg = g_off[n];
    const int end = g_off[n + 1];

    float s0 = 0.f, s1 = 0.f, s2 = 0.f, s3 = 0.f;
    for (int e = beg + lane; e < end; e += 32) {
        const int s = __ldg(&g_csr_src[e]);
        const float ww = __ldg(&g_csr_w[e]);
        float4 tv = *reinterpret_cast<const float4*>(&g_T[(size_t)s * 4]);
        s0 += ww * tv.x;
        s1 += ww * tv.y;
        s2 += ww * tv.z;
        s3 += ww * tv.w;
    }
#pragma unroll
    for (int off = 16; off > 0; off >>= 1) {
        s0 += __shfl_down_sync(0xFFFFFFFFu, s0, off);
        s1 += __shfl_down_sync(0xFFFFFFFFu, s1, off);
        s2 += __shfl_down_sync(0xFFFFFFFFu, s2, off);
        s3 += __shfl_down_sync(0xFFFFFFFFu, s3, off);
    }
    if (lane == 0) {
        float za0 = s0 + b2a[0], za1 = s1 + b2a[1];
        float ma = fmaxf(za0, za1);
        float ea0 = expf(za0 - ma), ea1 = expf(za1 - ma);
        float sa = ea0 + ea1;
        float p10 = ea0 / sa, p11 = ea1 / sa;
        float zb0 = s2 + b2b[0], zb1 = s3 + b2b[1];
        float mb = fmaxf(zb0, zb1);
        float eb0 = expf(zb0 - mb), eb1 = expf(zb1 - mb);
        float sb = eb0 + eb1;
        float p20 = eb0 / sb, p21 = eb1 / sb;
        float v0 = fmaxf(p10, p20);
        float v1 = fmaxf(p11, p21);
        float inv = 1.f / (v0 + v1);
        out[n * 2 + 0] = v0 * inv;
        out[n * 2 + 1] = v1 * inv;
    }
}

// ---------------------------------------------------------------------------
// Launch
// ---------------------------------------------------------------------------
extern "C" void kernel_launch(void* const* d_in, const int* in_sizes, int n_in,
                              void* d_out, int out_size) {
    const float* x        = (const float*)d_in[0];
    const int*   edge_src = (const int*)d_in[1];
    const int*   edge_dst = (const int*)d_in[2];
    const float* edge_w   = (const float*)d_in[3];
    const float* W1a      = (const float*)d_in[4];
    const float* b1a      = (const float*)d_in[5];
    const float* W2a      = (const float*)d_in[6];
    const float* b2a      = (const float*)d_in[7];
    const float* W1b      = (const float*)d_in[8];
    const float* b1b      = (const float*)d_in[9];
    const float* W2b      = (const float*)d_in[10];
    const float* b2b      = (const float*)d_in[11];
    float* out = (float*)d_out;

    // CSR build
    zero_counts_kernel<<<(NN + 255) / 256, 256>>>();
    hist_kernel<<<(NE + 255) / 256, 256>>>(edge_dst);
    scan_kernel<<<1, 1024>>>();
    fill_kernel<<<(NE + 255) / 256, 256>>>(edge_src, edge_dst, edge_w);

    // GEMM1 (tf32 tensor core)
    {
        dim3 grid(8, (NN + GBM - 1) / GBM);
        gemm1_tf32_kernel<<<grid, 256>>>(x, W1a, W1b);
    }

    // Fused aggregate + relu + projection -> T
    agg1_kernel<<<(NN + 7) / 8, 256>>>(b1a, W2a, b1b, W2b);

    // Fused aggregate2 + softmax + vote -> out
    agg2_kernel<<<(NN + 7) / 8, 256>>>(b2a, b2b, out);
}